// round 11
// baseline (speedup 1.0000x reference)
#include <cuda_runtime.h>
#include <cstdint>

// WordEmbedding: out[row, :] = W[ids[row], :]
//   W: [50257, 1024] fp32 (4KB rows), ids: [32768] int32, out: [32768,1024] fp32
//
// Persistent software-pipelined gather: one wave of CTAs; each CTA loops over
// 8-row tiles, issuing the NEXT tile's 8 gather loads before the CURRENT
// tile's stores, so the read pipe never drains. L2 policies: weight rows
// evict_last (pin ~96MB working set), output stream evict_first (dead data).

#define DIM 1024
#define VEC_PER_ROW (DIM / 4)   // 256 float4 per row
#define ROWS_PER_TILE 8

__device__ __forceinline__ void load_tile(const float4* __restrict__ w,
                                          const int* __restrict__ ids,
                                          int base_row, int t,
                                          unsigned long long pol_keep,
                                          float4 v[ROWS_PER_TILE])
{
    const int4* ids4 = (const int4*)(ids + base_row);
    const int4 ia = __ldg(&ids4[0]);
    const int4 ib = __ldg(&ids4[1]);
    const int id[ROWS_PER_TILE] = {ia.x, ia.y, ia.z, ia.w, ib.x, ib.y, ib.z, ib.w};
#pragma unroll
    for (int r = 0; r < ROWS_PER_TILE; r++) {
        const float4* p = w + (((size_t)id[r]) << 8) + t;
        asm volatile("ld.global.nc.L2::cache_hint.v4.f32 {%0,%1,%2,%3}, [%4], %5;"
                     : "=f"(v[r].x), "=f"(v[r].y), "=f"(v[r].z), "=f"(v[r].w)
                     : "l"(p), "l"(pol_keep));
    }
}

__device__ __forceinline__ void store_tile(float4* __restrict__ out,
                                           int base_row, int t,
                                           unsigned long long pol_drop,
                                           const float4 v[ROWS_PER_TILE])
{
#pragma unroll
    for (int r = 0; r < ROWS_PER_TILE; r++) {
        float4* q = out + (((size_t)(base_row + r)) << 8) + t;
        asm volatile("st.global.L2::cache_hint.v4.f32 [%0], {%1,%2,%3,%4}, %5;"
                     :: "l"(q), "f"(v[r].x), "f"(v[r].y), "f"(v[r].z), "f"(v[r].w),
                        "l"(pol_drop)
                     : "memory");
    }
}

__global__ __launch_bounds__(256)
void WordEmbedding_43181601194151_kernel(const float4* __restrict__ w,
                                         const int* __restrict__ ids,
                                         float4* __restrict__ out,
                                         int n_tiles)
{
    const int t = threadIdx.x;
    const int stride = gridDim.x;

    unsigned long long pol_keep, pol_drop;
    asm("createpolicy.fractional.L2::evict_last.b64  %0, 1.0;" : "=l"(pol_keep));
    asm("createpolicy.fractional.L2::evict_first.b64 %0, 1.0;" : "=l"(pol_drop));

    int tile = blockIdx.x;
    if (tile >= n_tiles) return;

    float4 va[ROWS_PER_TILE], vb[ROWS_PER_TILE];
    load_tile(w, ids, tile * ROWS_PER_TILE, t, pol_keep, va);

    for (;;) {
        const int next = tile + stride;
        if (next < n_tiles) {
            // Issue next tile's gathers BEFORE current stores: pipe stays full.
            load_tile(w, ids, next * ROWS_PER_TILE, t, pol_keep, vb);
            store_tile(out, tile * ROWS_PER_TILE, t, pol_drop, va);
            tile = next + stride;
            if (tile < n_tiles) {
                load_tile(w, ids, tile * ROWS_PER_TILE, t, pol_keep, va);
                store_tile(out, next * ROWS_PER_TILE, t, pol_drop, vb);
            } else {
                store_tile(out, next * ROWS_PER_TILE, t, pol_drop, vb);
                return;
            }
        } else {
            store_tile(out, tile * ROWS_PER_TILE, t, pol_drop, va);
            return;
        }
    }
}

extern "C" void kernel_launch(void* const* d_in, const int* in_sizes, int n_in,
                              void* d_out, int out_size)
{
    // Select inputs by size: the weight matrix is by far the larger tensor.
    int w_idx = 0, id_idx = 1;
    if (n_in >= 2 && in_sizes[1] > in_sizes[0]) { w_idx = 1; id_idx = 0; }

    const float4* w   = (const float4*)d_in[w_idx];
    const int*    ids = (const int*)d_in[id_idx];
    float4*       out = (float4*)d_out;

    const int n_rows  = out_size / DIM;               // 32768
    const int n_tiles = n_rows / ROWS_PER_TILE;       // 4096

    // One wave: 148 SMs x 8 CTAs (reg-limited lower in practice; grid-stride
    // loop makes any residency correct).
    const int n_blocks = 1184;

    WordEmbedding_43181601194151_kernel<<<n_blocks, 256>>>(w, ids, out, n_tiles);
}